// round 1
// baseline (speedup 1.0000x reference)
#include <cuda_runtime.h>
#include <math.h>

#define N_NODES 2048
#define NFEAT   512
#define NHID    128
#define NHEADS  4
#define NP      3
#define SHID    128
#define PH      (NP * NHEADS)     // 12
#define ALPHA_L 0.2f
#define NEGV    -9.0e15f

// ---------------- scratch (static device globals; no runtime alloc) --------
__device__ float g_h [PH * N_NODES * NHID];            // h[p,head][n][d]
__device__ float g_s [PH * N_NODES];                   // h . a_src
__device__ float g_dv[PH * N_NODES];                   // h . a_dst
__device__ float g_mx[PH * N_NODES];                   // row max of masked e
__device__ float g_iv[PH * N_NODES];                   // 1 / row sum exp
__device__ float g_m [NP * N_NODES * NHEADS * NHID];   // m[p][n][head*128+d]
__device__ float g_hs[NP * N_NODES * SHID];            // pre-tanh semantic
__device__ float g_sc[NP];                             // score accumulators
__device__ float g_w [NP];                             // semantic weights

// ---------------- generic 64x64-tile fp32 GEMM, K=512, ldb=ldc=128 ---------
__device__ __forceinline__ void gemm_body(const float* __restrict__ A,
                                          const float* __restrict__ B,
                                          float* __restrict__ C) {
    const int tm = blockIdx.y * 64;
    const int tn = blockIdx.x * 64;
    __shared__ float As[64][17];
    __shared__ float Bs[16][68];
    const int tid = threadIdx.x;
    const int tr = tid >> 4, tc = tid & 15;
    const int arow = tid >> 2, acb = (tid & 3) * 4;
    const int brow = tid >> 4, bcb = (tid & 15) * 4;
    float acc[4][4] = {};
    for (int k0 = 0; k0 < 512; k0 += 16) {
        __syncthreads();
        float4 av = *(const float4*)&A[(long)(tm + arow) * 512 + k0 + acb];
        As[arow][acb + 0] = av.x; As[arow][acb + 1] = av.y;
        As[arow][acb + 2] = av.z; As[arow][acb + 3] = av.w;
        float4 bv = *(const float4*)&B[(long)(k0 + brow) * 128 + tn + bcb];
        *(float4*)&Bs[brow][bcb] = bv;
        __syncthreads();
#pragma unroll
        for (int k = 0; k < 16; k++) {
            float a0 = As[tr * 4 + 0][k];
            float a1 = As[tr * 4 + 1][k];
            float a2 = As[tr * 4 + 2][k];
            float a3 = As[tr * 4 + 3][k];
            float4 bb = *(const float4*)&Bs[k][tc * 4];
            acc[0][0] += a0 * bb.x; acc[0][1] += a0 * bb.y; acc[0][2] += a0 * bb.z; acc[0][3] += a0 * bb.w;
            acc[1][0] += a1 * bb.x; acc[1][1] += a1 * bb.y; acc[1][2] += a1 * bb.z; acc[1][3] += a1 * bb.w;
            acc[2][0] += a2 * bb.x; acc[2][1] += a2 * bb.y; acc[2][2] += a2 * bb.z; acc[2][3] += a2 * bb.w;
            acc[3][0] += a3 * bb.x; acc[3][1] += a3 * bb.y; acc[3][2] += a3 * bb.z; acc[3][3] += a3 * bb.w;
        }
    }
#pragma unroll
    for (int r = 0; r < 4; r++) {
        float4 o = make_float4(acc[r][0], acc[r][1], acc[r][2], acc[r][3]);
        *(float4*)&C[(long)(tm + tr * 4 + r) * 128 + tn + tc * 4] = o;
    }
}

__global__ void __launch_bounds__(256) gemm_h_kernel(const float* __restrict__ x,
                                                     const float* __restrict__ Wn) {
    int b = blockIdx.z;
    gemm_body(x, Wn + (long)b * NFEAT * NHID, g_h + (long)b * N_NODES * NHID);
}

__global__ void __launch_bounds__(256) gemm_sem_kernel(const float* __restrict__ Ws) {
    gemm_body(g_m, Ws, g_hs);
}

// ---------------- s,d = h . a_src / a_dst ----------------------------------
__global__ void __launch_bounds__(256) sd_kernel(const float* __restrict__ a_node) {
    int gwarp = (blockIdx.x * 256 + threadIdx.x) >> 5;
    int lane = threadIdx.x & 31;
    if (gwarp >= PH * N_NODES) return;
    int ph = gwarp / N_NODES;
    const float* hrow = g_h + (long)gwarp * NHID;
    const float* asrc = a_node + (long)ph * 2 * NHID;
    const float* adst = asrc + NHID;
    float ss = 0.f, dd = 0.f;
#pragma unroll
    for (int k = lane; k < NHID; k += 32) {
        float hv = hrow[k];
        ss += hv * asrc[k];
        dd += hv * adst[k];
    }
#pragma unroll
    for (int o = 16; o; o >>= 1) {
        ss += __shfl_xor_sync(0xffffffffu, ss, o);
        dd += __shfl_xor_sync(0xffffffffu, dd, o);
    }
    if (!lane) { g_s[gwarp] = ss; g_dv[gwarp] = dd; }
}

// ---------------- per-row softmax stats (max, 1/sum) -----------------------
__global__ void __launch_bounds__(256) stats_kernel(const float* __restrict__ adjs) {
    const int ph = blockIdx.y;
    const int p = ph / NHEADS;
    __shared__ float ds[N_NODES];
    for (int j = threadIdx.x; j < N_NODES; j += 256)
        ds[j] = g_dv[(long)ph * N_NODES + j];
    __syncthreads();
    const int wid = threadIdx.x >> 5, lane = threadIdx.x & 31;
    const int row = blockIdx.x * 8 + wid;
    const float sv = g_s[(long)ph * N_NODES + row];
    const float* arow = adjs + ((long)p * N_NODES + row) * N_NODES;

    float mx = NEGV;
    for (int j = lane; j < N_NODES; j += 32) {
        if (arow[j] > 0.f) {
            float e = sv + ds[j];
            e = e > 0.f ? e : ALPHA_L * e;
            mx = fmaxf(mx, e);
        }
    }
#pragma unroll
    for (int o = 16; o; o >>= 1) mx = fmaxf(mx, __shfl_xor_sync(0xffffffffu, mx, o));

    float sum = 0.f;
    for (int j = lane; j < N_NODES; j += 32) {
        float e;
        if (arow[j] > 0.f) {
            e = sv + ds[j];
            e = e > 0.f ? e : ALPHA_L * e;
        } else e = NEGV;
        float t = e - mx;
        sum += (t < -80.f) ? 0.f : __expf(t);
    }
#pragma unroll
    for (int o = 16; o; o >>= 1) sum += __shfl_xor_sync(0xffffffffu, sum, o);

    if (!lane) {
        g_mx[(long)ph * N_NODES + row] = mx;
        g_iv[(long)ph * N_NODES + row] = 1.f / sum;
    }
}

// ---------------- fused attention: hp = ELU( softmax(masked e) @ h ) -------
// CTA: 64 rows of one (p,head); loop j-tiles of 32; att tile in smem; write m.
__global__ void __launch_bounds__(256) attn_kernel(const float* __restrict__ adjs) {
    const int ph = blockIdx.y;
    const int p = ph >> 2;
    const int head = ph & 3;
    const int tm = blockIdx.x * 64;
    __shared__ float att_s[64][33];
    __shared__ float h_s[32][128];
    __shared__ float ssm[64], mxm[64], ivm[64], dsm[32];
    const int tid = threadIdx.x;
    if (tid < 64) {
        long ri = (long)ph * N_NODES + tm + tid;
        ssm[tid] = g_s[ri];
        mxm[tid] = g_mx[ri];
        ivm[tid] = g_iv[ri];
    }
    const int tr = tid >> 4, tc = tid & 15;
    float acc[4][8] = {};
    const float* hbase = g_h + (long)ph * N_NODES * NHID;
    const float* abase = adjs + ((long)p * N_NODES + tm) * N_NODES;

    for (int j0 = 0; j0 < N_NODES; j0 += 32) {
        __syncthreads();  // previous tile fully consumed (also covers ssm on iter 0)
        if (tid < 32) dsm[tid] = g_dv[(long)ph * N_NODES + j0 + tid];
        // load h tile 32x128
#pragma unroll
        for (int it = 0; it < 4; it++) {
            int r = it * 8 + (tid >> 5);
            float4 hv = *(const float4*)&hbase[(long)(j0 + r) * 128 + (tid & 31) * 4];
            *(float4*)&h_s[r][(tid & 31) * 4] = hv;
        }
        __syncthreads();  // dsm visible
        // build att tile 64x32
#pragma unroll
        for (int it = 0; it < 8; it++) {
            int idx = it * 256 + tid;
            int i = idx >> 5, j = idx & 31;
            float a = abase[(long)i * N_NODES + j0 + j];
            float v = ssm[i] + dsm[j];
            v = v > 0.f ? v : ALPHA_L * v;
            float e = a > 0.f ? v : NEGV;
            float t = e - mxm[i];
            att_s[i][j] = (t < -80.f) ? 0.f : __expf(t) * ivm[i];
        }
        __syncthreads();  // att tile visible
#pragma unroll 8
        for (int k = 0; k < 32; k++) {
            float4 b0 = *(const float4*)&h_s[k][tc * 8];
            float4 b1 = *(const float4*)&h_s[k][tc * 8 + 4];
            float a0 = att_s[tr * 4 + 0][k];
            float a1 = att_s[tr * 4 + 1][k];
            float a2 = att_s[tr * 4 + 2][k];
            float a3 = att_s[tr * 4 + 3][k];
            acc[0][0] += a0 * b0.x; acc[0][1] += a0 * b0.y; acc[0][2] += a0 * b0.z; acc[0][3] += a0 * b0.w;
            acc[0][4] += a0 * b1.x; acc[0][5] += a0 * b1.y; acc[0][6] += a0 * b1.z; acc[0][7] += a0 * b1.w;
            acc[1][0] += a1 * b0.x; acc[1][1] += a1 * b0.y; acc[1][2] += a1 * b0.z; acc[1][3] += a1 * b0.w;
            acc[1][4] += a1 * b1.x; acc[1][5] += a1 * b1.y; acc[1][6] += a1 * b1.z; acc[1][7] += a1 * b1.w;
            acc[2][0] += a2 * b0.x; acc[2][1] += a2 * b0.y; acc[2][2] += a2 * b0.z; acc[2][3] += a2 * b0.w;
            acc[2][4] += a2 * b1.x; acc[2][5] += a2 * b1.y; acc[2][6] += a2 * b1.z; acc[2][7] += a2 * b1.w;
            acc[3][0] += a3 * b0.x; acc[3][1] += a3 * b0.y; acc[3][2] += a3 * b0.z; acc[3][3] += a3 * b0.w;
            acc[3][4] += a3 * b1.x; acc[3][5] += a3 * b1.y; acc[3][6] += a3 * b1.z; acc[3][7] += a3 * b1.w;
        }
    }
    // ELU epilogue, write directly into m[p][n][head*128 + d]
#pragma unroll
    for (int r = 0; r < 4; r++) {
        float o[8];
#pragma unroll
        for (int c = 0; c < 8; c++) {
            float v = acc[r][c];
            o[c] = v > 0.f ? v : expm1f(v);
        }
        long base = ((long)p * N_NODES + tm + tr * 4 + r) * (NHEADS * NHID) + head * NHID + tc * 8;
        *(float4*)&g_m[base]     = make_float4(o[0], o[1], o[2], o[3]);
        *(float4*)&g_m[base + 4] = make_float4(o[4], o[5], o[6], o[7]);
    }
}

// ---------------- semantic scores ------------------------------------------
__global__ void zero_scores() {
    if (threadIdx.x < NP) g_sc[threadIdx.x] = 0.f;
}

__global__ void __launch_bounds__(128) score_reduce(const float* __restrict__ b_sem,
                                                    const float* __restrict__ q_sem) {
    const int row = blockIdx.x;          // 0 .. NP*N-1
    const int j = threadIdx.x;           // 0 .. 127
    float v = g_hs[(long)row * SHID + j] + b_sem[j];
    float t = tanhf(v) * q_sem[j];
    __shared__ float red[128];
    red[j] = t;
    __syncthreads();
#pragma unroll
    for (int s = 64; s; s >>= 1) {
        if (j < s) red[j] += red[j + s];
        __syncthreads();
    }
    if (j == 0) atomicAdd(&g_sc[row >> 11], red[0]);
}

__global__ void wsoftmax() {
    if (threadIdx.x == 0) {
        float s0 = g_sc[0] / (float)N_NODES;
        float s1 = g_sc[1] / (float)N_NODES;
        float s2 = g_sc[2] / (float)N_NODES;
        float mx = fmaxf(s0, fmaxf(s1, s2));
        float e0 = expf(s0 - mx), e1 = expf(s1 - mx), e2 = expf(s2 - mx);
        float inv = 1.f / (e0 + e1 + e2);
        g_w[0] = e0 * inv; g_w[1] = e1 * inv; g_w[2] = e2 * inv;
    }
}

__global__ void __launch_bounds__(256) combine(float* __restrict__ out) {
    int i = blockIdx.x * 256 + threadIdx.x;
    const long S = (long)N_NODES * NHEADS * NHID;
    if (i < S) {
        out[i] = g_w[0] * g_m[i] + g_w[1] * g_m[S + i] + g_w[2] * g_m[2 * S + i];
    }
}

// ---------------- launch ----------------------------------------------------
extern "C" void kernel_launch(void* const* d_in, const int* in_sizes, int n_in,
                              void* d_out, int out_size) {
    const float* x      = (const float*)d_in[0];
    const float* adjs   = (const float*)d_in[1];
    const float* W_node = (const float*)d_in[2];
    const float* a_node = (const float*)d_in[3];
    const float* W_sem  = (const float*)d_in[4];
    const float* b_sem  = (const float*)d_in[5];
    const float* q_sem  = (const float*)d_in[6];
    float* out = (float*)d_out;

    zero_scores<<<1, 32>>>();

    // h[p,head] = x @ W_node[p,head]   (2048x512x128, 12 batches)
    gemm_h_kernel<<<dim3(2, N_NODES / 64, PH), 256>>>(x, W_node);

    // s, d vectors
    sd_kernel<<<(PH * N_NODES) / 8, 256>>>(a_node);

    // per-row masked softmax stats
    stats_kernel<<<dim3(N_NODES / 8, PH), 256>>>(adjs);

    // fused masked attention GEMM + ELU -> m
    attn_kernel<<<dim3(N_NODES / 64, PH), 256>>>(adjs);

    // semantic pre-activation: m_flat @ W_sem  (6144x512x128)
    gemm_sem_kernel<<<dim3(2, (NP * N_NODES) / 64, 1), 256>>>(W_sem);

    // scores -> w
    score_reduce<<<NP * N_NODES, 128>>>(b_sem, q_sem);
    wsoftmax<<<1, 32>>>();

    // out = sum_p w_p * m_p
    combine<<<(N_NODES * NHEADS * NHID + 255) / 256, 256>>>(out);
}

// round 2
// speedup vs baseline: 3.0947x; 3.0947x over previous
#include <cuda_runtime.h>
#include <math.h>

#define N_NODES 2048
#define NFEAT   512
#define NHID    128
#define NHEADS  4
#define NP      3
#define SHID    128
#define PH      (NP * NHEADS)     // 12
#define ALPHA_L 0.2f
#define NEGV    -9.0e15f

// ---------------- scratch (static device globals; no runtime alloc) --------
__device__ float g_h [PH * N_NODES * NHID];            // h[p,head][n][d]
__device__ float g_s [PH * N_NODES];                   // h . a_src
__device__ float g_dv[PH * N_NODES];                   // h . a_dst
__device__ float g_mx[PH * N_NODES];                   // row max of masked e
__device__ float g_iv[PH * N_NODES];                   // 1 / row sum exp
__device__ float g_m [NP * N_NODES * NHEADS * NHID];   // m[p][n][head*128+d]
__device__ float g_hs[NP * N_NODES * SHID];            // pre-tanh semantic
__device__ float g_sc[NP];                             // score accumulators
__device__ float g_w [NP];                             // semantic weights

// ---------------- tf32 helpers ---------------------------------------------
__device__ __forceinline__ unsigned f2tf(float f) {
    unsigned r;
    asm("cvt.rna.tf32.f32 %0, %1;" : "=r"(r) : "f"(f));
    return r;
}

__device__ __forceinline__ void mma8(float* c,
                                     unsigned a0, unsigned a1, unsigned a2, unsigned a3,
                                     unsigned b0, unsigned b1) {
    asm volatile("mma.sync.aligned.m16n8k8.row.col.f32.tf32.tf32.f32 "
                 "{%0,%1,%2,%3}, {%4,%5,%6,%7}, {%8,%9}, {%0,%1,%2,%3};"
                 : "+f"(c[0]), "+f"(c[1]), "+f"(c[2]), "+f"(c[3])
                 : "r"(a0), "r"(a1), "r"(a2), "r"(a3), "r"(b0), "r"(b1));
}

// ---------------- tf32 tensor-core GEMM body: C[64x128] tile, ldb=ldc=128 --
// 8 warps: 4 along M (16 rows each) x 2 along N (64 cols each).
__device__ __forceinline__ void gemm_body(const float* __restrict__ A, int lda,
                                          const float* __restrict__ B,
                                          float* __restrict__ C, int K) {
    const int tm = blockIdx.x * 64;
    __shared__ unsigned As[64][36];    // +4 pad: (36r+k)%32 = lane -> conflict-free
    __shared__ unsigned Bs[32][136];   // +8 pad: (136k+n)%32 = (8k+n) -> conflict-free
    const int tid = threadIdx.x;
    const int warp = tid >> 5, lane = tid & 31;
    const int wi = warp & 3, wj = warp >> 2;
    const int la = lane >> 2, lb = lane & 3;
    float acc[8][4] = {};

    for (int k0 = 0; k0 < K; k0 += 32) {
        __syncthreads();
        // A tile 64x32 (2 float4/thread)
#pragma unroll
        for (int it = 0; it < 2; it++) {
            int u = it * 256 + tid;
            int row = u >> 3, c4 = (u & 7) * 4;
            float4 v = *(const float4*)&A[(long)(tm + row) * lda + k0 + c4];
            As[row][c4 + 0] = f2tf(v.x); As[row][c4 + 1] = f2tf(v.y);
            As[row][c4 + 2] = f2tf(v.z); As[row][c4 + 3] = f2tf(v.w);
        }
        // B tile 32x128 (4 float4/thread)
#pragma unroll
        for (int it = 0; it < 4; it++) {
            int r = it * 8 + (tid >> 5), c4 = (tid & 31) * 4;
            float4 v = *(const float4*)&B[(long)(k0 + r) * 128 + c4];
            Bs[r][c4 + 0] = f2tf(v.x); Bs[r][c4 + 1] = f2tf(v.y);
            Bs[r][c4 + 2] = f2tf(v.z); Bs[r][c4 + 3] = f2tf(v.w);
        }
        __syncthreads();
#pragma unroll
        for (int ks = 0; ks < 4; ks++) {
            int kk = ks * 8;
            unsigned a0 = As[wi * 16 + la][kk + lb];
            unsigned a1 = As[wi * 16 + la + 8][kk + lb];
            unsigned a2 = As[wi * 16 + la][kk + lb + 4];
            unsigned a3 = As[wi * 16 + la + 8][kk + lb + 4];
#pragma unroll
            for (int nt = 0; nt < 8; nt++) {
                int cn = wj * 64 + nt * 8 + la;
                unsigned b0 = Bs[kk + lb][cn];
                unsigned b1 = Bs[kk + lb + 4][cn];
                mma8(acc[nt], a0, a1, a2, a3, b0, b1);
            }
        }
    }
    const int row = tm + wi * 16 + la;
    const int colb = wj * 64 + lb * 2;
#pragma unroll
    for (int nt = 0; nt < 8; nt++) {
        int col = colb + nt * 8;
        *(float2*)&C[(long)row * 128 + col]       = make_float2(acc[nt][0], acc[nt][1]);
        *(float2*)&C[(long)(row + 8) * 128 + col] = make_float2(acc[nt][2], acc[nt][3]);
    }
}

__global__ void __launch_bounds__(256) gemm_h_kernel(const float* __restrict__ x,
                                                     const float* __restrict__ Wn) {
    int b = blockIdx.y;
    gemm_body(x, NFEAT, Wn + (long)b * NFEAT * NHID, g_h + (long)b * N_NODES * NHID, NFEAT);
}

__global__ void __launch_bounds__(256) gemm_sem_kernel(const float* __restrict__ Ws) {
    gemm_body(g_m, NHEADS * NHID, Ws, g_hs, NHEADS * NHID);
}

// ---------------- s,d = h . a_src / a_dst ----------------------------------
__global__ void __launch_bounds__(256) sd_kernel(const float* __restrict__ a_node) {
    int gwarp = (blockIdx.x * 256 + threadIdx.x) >> 5;
    int lane = threadIdx.x & 31;
    if (gwarp >= PH * N_NODES) return;
    int ph = gwarp / N_NODES;
    const float* hrow = g_h + (long)gwarp * NHID;
    const float* asrc = a_node + (long)ph * 2 * NHID;
    const float* adst = asrc + NHID;
    float4 hv = *(const float4*)&hrow[lane * 4];
    float4 as = *(const float4*)&asrc[lane * 4];
    float4 ad = *(const float4*)&adst[lane * 4];
    float ss = hv.x * as.x + hv.y * as.y + hv.z * as.z + hv.w * as.w;
    float dd = hv.x * ad.x + hv.y * ad.y + hv.z * ad.z + hv.w * ad.w;
#pragma unroll
    for (int o = 16; o; o >>= 1) {
        ss += __shfl_xor_sync(0xffffffffu, ss, o);
        dd += __shfl_xor_sync(0xffffffffu, dd, o);
    }
    if (!lane) { g_s[gwarp] = ss; g_dv[gwarp] = dd; }
}

// ---------------- per-row softmax stats (max, 1/sum) -----------------------
// lrelu is monotone: row max = lrelu(s_i + max_{adj} d_j).
__global__ void __launch_bounds__(256) stats_kernel(const float* __restrict__ adjs) {
    const int ph = blockIdx.y;
    const int p = ph >> 2;
    __shared__ float ds[N_NODES];
    for (int j = threadIdx.x; j < N_NODES; j += 256)
        ds[j] = g_dv[(long)ph * N_NODES + j];
    __syncthreads();
    const int wid = threadIdx.x >> 5, lane = threadIdx.x & 31;
    const int row = blockIdx.x * 8 + wid;
    const float sv = g_s[(long)ph * N_NODES + row];
    const float* arow = adjs + ((long)p * N_NODES + row) * N_NODES;

    float md = -INFINITY;
#pragma unroll 4
    for (int it = 0; it < 16; it++) {
        int j = it * 128 + lane * 4;
        float4 a = *(const float4*)&arow[j];
        float4 d = *(const float4*)&ds[j];
        if (a.x > 0.f) md = fmaxf(md, d.x);
        if (a.y > 0.f) md = fmaxf(md, d.y);
        if (a.z > 0.f) md = fmaxf(md, d.z);
        if (a.w > 0.f) md = fmaxf(md, d.w);
    }
#pragma unroll
    for (int o = 16; o; o >>= 1) md = fmaxf(md, __shfl_xor_sync(0xffffffffu, md, o));

    float mx, isum;
    if (md == -INFINITY) {                    // fully masked row -> uniform
        mx = NEGV; isum = 1.f / (float)N_NODES;
    } else {
        float v = sv + md;
        mx = v > 0.f ? v : ALPHA_L * v;
        float sum = 0.f;
#pragma unroll 4
        for (int it = 0; it < 16; it++) {
            int j = it * 128 + lane * 4;
            float4 a = *(const float4*)&arow[j];
            float4 d = *(const float4*)&ds[j];
            float e;
            e = sv + d.x; e = e > 0.f ? e : ALPHA_L * e; if (a.x > 0.f) sum += __expf(e - mx);
            e = sv + d.y; e = e > 0.f ? e : ALPHA_L * e; if (a.y > 0.f) sum += __expf(e - mx);
            e = sv + d.z; e = e > 0.f ? e : ALPHA_L * e; if (a.z > 0.f) sum += __expf(e - mx);
            e = sv + d.w; e = e > 0.f ? e : ALPHA_L * e; if (a.w > 0.f) sum += __expf(e - mx);
        }
#pragma unroll
        for (int o = 16; o; o >>= 1) sum += __shfl_xor_sync(0xffffffffu, sum, o);
        isum = 1.f / sum;
    }
    if (!lane) {
        g_mx[(long)ph * N_NODES + row] = mx;
        g_iv[(long)ph * N_NODES + row] = isum;
    }
}

// ---------------- fused attention: hp = ELU( softmax(masked e) @ h ) -------
// tf32 tensor-core version. CTA: 64 rows x 128 cols of one (p,head).
__global__ void __launch_bounds__(256) attn_kernel(const float* __restrict__ adjs) {
    const int ph = blockIdx.y;
    const int p = ph >> 2;
    const int head = ph & 3;
    const int tm = blockIdx.x * 64;
    __shared__ unsigned att_s[64][36];
    __shared__ unsigned h_s[32][136];
    __shared__ float ssm[64], mxm[64], ivm[64], dsm[32];
    const int tid = threadIdx.x;
    const int warp = tid >> 5, lane = tid & 31;
    const int wi = warp & 3, wj = warp >> 2;
    const int la = lane >> 2, lb = lane & 3;
    if (tid < 64) {
        long ri = (long)ph * N_NODES + tm + tid;
        ssm[tid] = g_s[ri];
        mxm[tid] = g_mx[ri];
        ivm[tid] = g_iv[ri];
    }
    float acc[8][4] = {};
    const float* hbase = g_h + (long)ph * N_NODES * NHID;
    const float* abase = adjs + ((long)p * N_NODES + tm) * N_NODES;

    for (int j0 = 0; j0 < N_NODES; j0 += 32) {
        __syncthreads();   // prev tile consumed (covers ssm/mxm/ivm on iter 0)
        if (tid < 32) dsm[tid] = g_dv[(long)ph * N_NODES + j0 + tid];
        // h tile 32x128 -> tf32
#pragma unroll
        for (int it = 0; it < 4; it++) {
            int r = it * 8 + (tid >> 5), c4 = (tid & 31) * 4;
            float4 hv = *(const float4*)&hbase[(long)(j0 + r) * 128 + c4];
            h_s[r][c4 + 0] = f2tf(hv.x); h_s[r][c4 + 1] = f2tf(hv.y);
            h_s[r][c4 + 2] = f2tf(hv.z); h_s[r][c4 + 3] = f2tf(hv.w);
        }
        __syncthreads();   // dsm + h visible
        // att tile 64x32 (float4 over j)
#pragma unroll
        for (int it = 0; it < 2; it++) {
            int idx = it * 256 + tid;
            int i = idx >> 3, j4 = (idx & 7) * 4;
            float4 a = *(const float4*)&abase[(long)i * N_NODES + j0 + j4];
            float sv = ssm[i], mv = mxm[i], iv = ivm[i];
            float aa[4] = {a.x, a.y, a.z, a.w};
            unsigned o[4];
#pragma unroll
            for (int q = 0; q < 4; q++) {
                float v = sv + dsm[j4 + q];
                v = v > 0.f ? v : ALPHA_L * v;
                float e = aa[q] > 0.f ? v : NEGV;
                float t = e - mv;
                float r = (t < -80.f) ? 0.f : __expf(t) * iv;
                o[q] = f2tf(r);
            }
            *(uint4*)&att_s[i][j4] = make_uint4(o[0], o[1], o[2], o[3]);
        }
        __syncthreads();   // att tile visible
#pragma unroll
        for (int ks = 0; ks < 4; ks++) {
            int kk = ks * 8;
            unsigned a0 = att_s[wi * 16 + la][kk + lb];
            unsigned a1 = att_s[wi * 16 + la + 8][kk + lb];
            unsigned a2 = att_s[wi * 16 + la][kk + lb + 4];
            unsigned a3 = att_s[wi * 16 + la + 8][kk + lb + 4];
#pragma unroll
            for (int nt = 0; nt < 8; nt++) {
                int cn = wj * 64 + nt * 8 + la;
                unsigned b0 = h_s[kk + lb][cn];
                unsigned b1 = h_s[kk + lb + 4][cn];
                mma8(acc[nt], a0, a1, a2, a3, b0, b1);
            }
        }
    }
    // ELU epilogue, write into m[p][n][head*128 + d]
    const int row = tm + wi * 16 + la;
    const int colb = wj * 64 + lb * 2;
#pragma unroll
    for (int nt = 0; nt < 8; nt++) {
        int col = head * 128 + colb + nt * 8;
        float e0 = acc[nt][0] > 0.f ? acc[nt][0] : expm1f(acc[nt][0]);
        float e1 = acc[nt][1] > 0.f ? acc[nt][1] : expm1f(acc[nt][1]);
        float e2 = acc[nt][2] > 0.f ? acc[nt][2] : expm1f(acc[nt][2]);
        float e3 = acc[nt][3] > 0.f ? acc[nt][3] : expm1f(acc[nt][3]);
        long b0i = ((long)p * N_NODES + row) * (NHEADS * NHID) + col;
        long b1i = ((long)p * N_NODES + row + 8) * (NHEADS * NHID) + col;
        *(float2*)&g_m[b0i] = make_float2(e0, e1);
        *(float2*)&g_m[b1i] = make_float2(e2, e3);
    }
}

// ---------------- semantic scores ------------------------------------------
__global__ void zero_scores() {
    if (threadIdx.x < NP) g_sc[threadIdx.x] = 0.f;
}

__global__ void __launch_bounds__(128) score_reduce(const float* __restrict__ b_sem,
                                                    const float* __restrict__ q_sem) {
    const int row = blockIdx.x;          // 0 .. NP*N-1
    const int j = threadIdx.x;           // 0 .. 127
    float v = g_hs[(long)row * SHID + j] + b_sem[j];
    float t = tanhf(v) * q_sem[j];
    __shared__ float red[128];
    red[j] = t;
    __syncthreads();
#pragma unroll
    for (int s = 64; s; s >>= 1) {
        if (j < s) red[j] += red[j + s];
        __syncthreads();
    }
    if (j == 0) atomicAdd(&g_sc[row >> 11], red[0]);
}

__global__ void wsoftmax() {
    if (threadIdx.x == 0) {
        float s0 = g_sc[0] / (float)N_NODES;
        float s1 = g_sc[1] / (float)N_NODES;
        float s2 = g_sc[2] / (float)N_NODES;
        float mx = fmaxf(s0, fmaxf(s1, s2));
        float e0 = expf(s0 - mx), e1 = expf(s1 - mx), e2 = expf(s2 - mx);
        float inv = 1.f / (e0 + e1 + e2);
        g_w[0] = e0 * inv; g_w[1] = e1 * inv; g_w[2] = e2 * inv;
    }
}

__global__ void __launch_bounds__(256) combine(float* __restrict__ out) {
    int i = blockIdx.x * 256 + threadIdx.x;
    const long S = (long)N_NODES * NHEADS * NHID;
    if (i < S) {
        out[i] = g_w[0] * g_m[i] + g_w[1] * g_m[S + i] + g_w[2] * g_m[2 * S + i];
    }
}

// ---------------- launch ----------------------------------------------------
extern "C" void kernel_launch(void* const* d_in, const int* in_sizes, int n_in,
                              void* d_out, int out_size) {
    const float* x      = (const float*)d_in[0];
    const float* adjs   = (const float*)d_in[1];
    const float* W_node = (const float*)d_in[2];
    const float* a_node = (const float*)d_in[3];
    const float* W_sem  = (const float*)d_in[4];
    const float* b_sem  = (const float*)d_in[5];
    const float* q_sem  = (const float*)d_in[6];
    float* out = (float*)d_out;

    zero_scores<<<1, 32>>>();

    // h[p,head] = x @ W_node[p,head]   (2048x512x128, 12 batches), tf32 MMA
    gemm_h_kernel<<<dim3(N_NODES / 64, PH), 256>>>(x, W_node);

    // s, d vectors
    sd_kernel<<<(PH * N_NODES) / 8, 256>>>(a_node);

    // per-row masked softmax stats
    stats_kernel<<<dim3(N_NODES / 8, PH), 256>>>(adjs);

    // fused masked attention GEMM + ELU -> m, tf32 MMA
    attn_kernel<<<dim3(N_NODES / 64, PH), 256>>>(adjs);

    // semantic pre-activation: m_flat @ W_sem  (6144x512x128), tf32 MMA
    gemm_sem_kernel<<<dim3((NP * N_NODES) / 64, 1), 256>>>(W_sem);

    // scores -> w
    score_reduce<<<NP * N_NODES, 128>>>(b_sem, q_sem);
    wsoftmax<<<1, 32>>>();

    // out = sum_p w_p * m_p
    combine<<<(N_NODES * NHEADS * NHID + 255) / 256, 256>>>(out);
}

// round 10
// speedup vs baseline: 3.4579x; 1.1173x over previous
#include <cuda_runtime.h>
#include <math.h>

#define N_NODES 2048
#define NFEAT   512
#define NHID    128
#define NHEADS  4
#define NP      3
#define SHID    128
#define PH      (NP * NHEADS)     // 12
#define ALPHA_L 0.2f
#define NEGV    -9.0e15f

// ---------------- scratch (static device globals; no runtime alloc) --------
__device__ float g_h [PH * N_NODES * NHID];            // h[p,head][n][d]
__device__ float g_s [PH * N_NODES];                   // h . a_src
__device__ float g_dv[PH * N_NODES];                   // h . a_dst
__device__ float g_m [NP * N_NODES * NHEADS * NHID];   // m[p][n][head*128+d]
__device__ float g_sc[NP];                             // score accumulators

// ---------------- tf32 helpers ---------------------------------------------
__device__ __forceinline__ unsigned f2tf(float f) {
    unsigned r;
    asm("cvt.rna.tf32.f32 %0, %1;" : "=r"(r) : "f"(f));
    return r;
}

__device__ __forceinline__ void mma8(float* c,
                                     unsigned a0, unsigned a1, unsigned a2, unsigned a3,
                                     unsigned b0, unsigned b1) {
    asm volatile("mma.sync.aligned.m16n8k8.row.col.f32.tf32.tf32.f32 "
                 "{%0,%1,%2,%3}, {%4,%5,%6,%7}, {%8,%9}, {%0,%1,%2,%3};"
                 : "+f"(c[0]), "+f"(c[1]), "+f"(c[2]), "+f"(c[3])
                 : "r"(a0), "r"(a1), "r"(a2), "r"(a3), "r"(b0), "r"(b1));
}

__device__ __forceinline__ float gexp(float t) {
    return t < -80.f ? 0.f : __expf(t);
}

// ---------------- tf32 GEMM core: 64x128 C tile, ldb=128, acc in regs ------
// 8 warps: 4 along M (16 rows each) x 2 along N (64 cols each).
__device__ __forceinline__ void gemm_core(const float* __restrict__ A, int lda,
                                          const float* __restrict__ B, int K,
                                          int tm, float acc[8][4]) {
    __shared__ unsigned As[64][36];    // +4 pad
    __shared__ unsigned Bs[32][136];   // +8 pad
    const int tid = threadIdx.x;
    const int warp = tid >> 5, lane = tid & 31;
    const int wi = warp & 3, wj = warp >> 2;
    const int la = lane >> 2, lb = lane & 3;

    for (int k0 = 0; k0 < K; k0 += 32) {
        __syncthreads();
#pragma unroll
        for (int it = 0; it < 2; it++) {
            int u = it * 256 + tid;
            int row = u >> 3, c4 = (u & 7) * 4;
            float4 v = *(const float4*)&A[(long)(tm + row) * lda + k0 + c4];
            As[row][c4 + 0] = f2tf(v.x); As[row][c4 + 1] = f2tf(v.y);
            As[row][c4 + 2] = f2tf(v.z); As[row][c4 + 3] = f2tf(v.w);
        }
#pragma unroll
        for (int it = 0; it < 4; it++) {
            int r = it * 8 + (tid >> 5), c4 = (tid & 31) * 4;
            float4 v = *(const float4*)&B[(long)(k0 + r) * 128 + c4];
            Bs[r][c4 + 0] = f2tf(v.x); Bs[r][c4 + 1] = f2tf(v.y);
            Bs[r][c4 + 2] = f2tf(v.z); Bs[r][c4 + 3] = f2tf(v.w);
        }
        __syncthreads();
#pragma unroll
        for (int ks = 0; ks < 4; ks++) {
            int kk = ks * 8;
            unsigned a0 = As[wi * 16 + la][kk + lb];
            unsigned a1 = As[wi * 16 + la + 8][kk + lb];
            unsigned a2 = As[wi * 16 + la][kk + lb + 4];
            unsigned a3 = As[wi * 16 + la + 8][kk + lb + 4];
#pragma unroll
            for (int nt = 0; nt < 8; nt++) {
                int cn = wj * 64 + nt * 8 + la;
                unsigned b0 = Bs[kk + lb][cn];
                unsigned b1 = Bs[kk + lb + 4][cn];
                mma8(acc[nt], a0, a1, a2, a3, b0, b1);
            }
        }
    }
}

// ---------------- h = x @ W_node (also zeroes g_sc) ------------------------
__global__ void __launch_bounds__(256) gemm_h_kernel(const float* __restrict__ x,
                                                     const float* __restrict__ Wn) {
    const int b = blockIdx.y;
    const int tm = blockIdx.x * 64;
    // zero score accumulators (g_sc not read until gemm_sem_fused, stream-ordered)
    if (blockIdx.x == 0 && blockIdx.y == 0 && threadIdx.x < NP)
        g_sc[threadIdx.x] = 0.f;
    float acc[8][4] = {};
    gemm_core(x, NFEAT, Wn + (long)b * NFEAT * NHID, NFEAT, tm, acc);
    float* C = g_h + (long)b * N_NODES * NHID;
    const int warp = threadIdx.x >> 5, lane = threadIdx.x & 31;
    const int wi = warp & 3, wj = warp >> 2;
    const int la = lane >> 2, lb = lane & 3;
    const int row = tm + wi * 16 + la;
    const int colb = wj * 64 + lb * 2;
#pragma unroll
    for (int nt = 0; nt < 8; nt++) {
        int col = colb + nt * 8;
        *(float2*)&C[(long)row * 128 + col]       = make_float2(acc[nt][0], acc[nt][1]);
        *(float2*)&C[(long)(row + 8) * 128 + col] = make_float2(acc[nt][2], acc[nt][3]);
    }
}

// ---------------- semantic GEMM fused with score reduction ------------------
// scores[p] += sum over rows,cols of tanh(m@W_sem + b)*q
__global__ void __launch_bounds__(256) gemm_sem_fused(const float* __restrict__ Ws,
                                                      const float* __restrict__ b_sem,
                                                      const float* __restrict__ q_sem) {
    const int tm = blockIdx.x * 64;
    const int p = tm >> 11;
    __shared__ float sred;
    if (threadIdx.x == 0) sred = 0.f;   // first sync inside gemm_core publishes
    float acc[8][4] = {};
    gemm_core(g_m, NHEADS * NHID, Ws, NHEADS * NHID, tm, acc);
    const int warp = threadIdx.x >> 5, lane = threadIdx.x & 31;
    const int wj = warp >> 2, lb = lane & 3;
    float s = 0.f;
#pragma unroll
    for (int nt = 0; nt < 8; nt++) {
        int col = wj * 64 + lb * 2 + nt * 8;
        float b0 = b_sem[col], b1 = b_sem[col + 1];
        float q0 = q_sem[col], q1 = q_sem[col + 1];
        s += tanhf(acc[nt][0] + b0) * q0 + tanhf(acc[nt][1] + b1) * q1;
        s += tanhf(acc[nt][2] + b0) * q0 + tanhf(acc[nt][3] + b1) * q1;
    }
#pragma unroll
    for (int o = 16; o; o >>= 1) s += __shfl_xor_sync(0xffffffffu, s, o);
    if (!lane) atomicAdd(&sred, s);
    __syncthreads();
    if (threadIdx.x == 0) atomicAdd(&g_sc[p], sred);
}

// ---------------- s,d = h . a_src / a_dst ----------------------------------
__global__ void __launch_bounds__(256) sd_kernel(const float* __restrict__ a_node) {
    int gwarp = (blockIdx.x * 256 + threadIdx.x) >> 5;
    int lane = threadIdx.x & 31;
    if (gwarp >= PH * N_NODES) return;
    int ph = gwarp / N_NODES;
    const float* hrow = g_h + (long)gwarp * NHID;
    const float* asrc = a_node + (long)ph * 2 * NHID;
    const float* adst = asrc + NHID;
    float4 hv = *(const float4*)&hrow[lane * 4];
    float4 as = *(const float4*)&asrc[lane * 4];
    float4 ad = *(const float4*)&adst[lane * 4];
    float ss = hv.x * as.x + hv.y * as.y + hv.z * as.z + hv.w * as.w;
    float dd = hv.x * ad.x + hv.y * ad.y + hv.z * ad.z + hv.w * ad.w;
#pragma unroll
    for (int o = 16; o; o >>= 1) {
        ss += __shfl_xor_sync(0xffffffffu, ss, o);
        dd += __shfl_xor_sync(0xffffffffu, dd, o);
    }
    if (!lane) { g_s[gwarp] = ss; g_dv[gwarp] = dd; }
}

// ---------------- fused attention, ONLINE softmax + tf32 MMA ---------------
// hp = ELU( softmax(mask(lrelu(s_i + d_j))) @ h ); no stats prepass.
__global__ void __launch_bounds__(256) attn_kernel(const float* __restrict__ adjs) {
    const int ph = blockIdx.y;
    const int p = ph >> 2;
    const int head = ph & 3;
    const int tm = blockIdx.x * 64;
    __shared__ unsigned att_s[64][36];
    __shared__ unsigned h_s[32][136];
    __shared__ float ssm[64], mxs[64], sms[64], rmx[64], dsm[32];
    const int tid = threadIdx.x;
    const int warp = tid >> 5, lane = tid & 31;
    const int wi = warp & 3, wj = warp >> 2;
    const int la = lane >> 2, lb = lane & 3;
    if (tid < 64) {
        ssm[tid] = g_s[(long)ph * N_NODES + tm + tid];
        mxs[tid] = NEGV;
        sms[tid] = 0.f;
        rmx[tid] = 1.f;
    }
    float acc[8][4] = {};
    const float* hbase = g_h + (long)ph * N_NODES * NHID;
    const float* abase = adjs + ((long)p * N_NODES + tm) * N_NODES;

    for (int j0 = 0; j0 < N_NODES; j0 += 32) {
        __syncthreads();   // prev tile consumed (covers init on iter 0)
        if (tid < 32) dsm[tid] = g_dv[(long)ph * N_NODES + j0 + tid];
        // h tile 32x128 -> tf32
#pragma unroll
        for (int it = 0; it < 4; it++) {
            int r = it * 8 + (tid >> 5), c4 = (tid & 31) * 4;
            float4 hv = *(const float4*)&hbase[(long)(j0 + r) * 128 + c4];
            h_s[r][c4 + 0] = f2tf(hv.x); h_s[r][c4 + 1] = f2tf(hv.y);
            h_s[r][c4 + 2] = f2tf(hv.z); h_s[r][c4 + 3] = f2tf(hv.w);
        }
        __syncthreads();   // dsm + h visible
        // online-softmax att tile 64x32 (8 threads per row, aligned segments)
#pragma unroll
        for (int it = 0; it < 2; it++) {
            int idx = it * 256 + tid;
            int i = idx >> 3, j4 = (idx & 7) * 4;
            float4 a = *(const float4*)&abase[(long)i * N_NODES + j0 + j4];
            float sv = ssm[i];
            float aa[4] = {a.x, a.y, a.z, a.w};
            float e[4];
#pragma unroll
            for (int q = 0; q < 4; q++) {
                float v = sv + dsm[j4 + q];
                v = v > 0.f ? v : ALPHA_L * v;
                e[q] = aa[q] > 0.f ? v : NEGV;
            }
            float tmax = fmaxf(fmaxf(e[0], e[1]), fmaxf(e[2], e[3]));
            tmax = fmaxf(tmax, __shfl_xor_sync(0xffffffffu, tmax, 1));
            tmax = fmaxf(tmax, __shfl_xor_sync(0xffffffffu, tmax, 2));
            tmax = fmaxf(tmax, __shfl_xor_sync(0xffffffffu, tmax, 4));
            float old = mxs[i];
            float newm = fmaxf(old, tmax);
            float r = gexp(old - newm);
            float ts = 0.f;
            unsigned o[4];
#pragma unroll
            for (int q = 0; q < 4; q++) {
                float pq = gexp(e[q] - newm);
                ts += pq;
                o[q] = f2tf(pq);
            }
            *(uint4*)&att_s[i][j4] = make_uint4(o[0], o[1], o[2], o[3]);
            ts += __shfl_xor_sync(0xffffffffu, ts, 1);
            ts += __shfl_xor_sync(0xffffffffu, ts, 2);
            ts += __shfl_xor_sync(0xffffffffu, ts, 4);
            if ((tid & 7) == 0) {
                mxs[i] = newm;
                rmx[i] = r;
                sms[i] = sms[i] * r + ts;
            }
        }
        __syncthreads();   // att tile + rmx visible
        // rescale accumulators, then MMA
        {
            float r0 = rmx[wi * 16 + la];
            float r1 = rmx[wi * 16 + la + 8];
#pragma unroll
            for (int nt = 0; nt < 8; nt++) {
                acc[nt][0] *= r0; acc[nt][1] *= r0;
                acc[nt][2] *= r1; acc[nt][3] *= r1;
            }
        }
#pragma unroll
        for (int ks = 0; ks < 4; ks++) {
            int kk = ks * 8;
            unsigned a0 = att_s[wi * 16 + la][kk + lb];
            unsigned a1 = att_s[wi * 16 + la + 8][kk + lb];
            unsigned a2 = att_s[wi * 16 + la][kk + lb + 4];
            unsigned a3 = att_s[wi * 16 + la + 8][kk + lb + 4];
#pragma unroll
            for (int nt = 0; nt < 8; nt++) {
                int cn = wj * 64 + nt * 8 + la;
                unsigned b0 = h_s[kk + lb][cn];
                unsigned b1 = h_s[kk + lb + 4][cn];
                mma8(acc[nt], a0, a1, a2, a3, b0, b1);
            }
        }
    }
    // normalize + ELU epilogue, write into m[p][n][head*128 + d]
    const int row = tm + wi * 16 + la;
    const int colb = wj * 64 + lb * 2;
    const float inv0 = 1.f / sms[wi * 16 + la];
    const float inv1 = 1.f / sms[wi * 16 + la + 8];
#pragma unroll
    for (int nt = 0; nt < 8; nt++) {
        int col = head * 128 + colb + nt * 8;
        float v0 = acc[nt][0] * inv0, v1 = acc[nt][1] * inv0;
        float v2 = acc[nt][2] * inv1, v3 = acc[nt][3] * inv1;
        float e0 = v0 > 0.f ? v0 : expm1f(v0);
        float e1 = v1 > 0.f ? v1 : expm1f(v1);
        float e2 = v2 > 0.f ? v2 : expm1f(v2);
        float e3 = v3 > 0.f ? v3 : expm1f(v3);
        long b0i = ((long)p * N_NODES + row) * (NHEADS * NHID) + col;
        long b1i = ((long)p * N_NODES + row + 8) * (NHEADS * NHID) + col;
        *(float2*)&g_m[b0i] = make_float2(e0, e1);
        *(float2*)&g_m[b1i] = make_float2(e2, e3);
    }
}

// ---------------- combine (w softmax computed inline) -----------------------
__global__ void __launch_bounds__(256) combine(float* __restrict__ out) {
    int i = blockIdx.x * 256 + threadIdx.x;
    const long S = (long)N_NODES * NHEADS * NHID;
    if (i < S) {
        float s0 = g_sc[0] * (1.f / (float)N_NODES);
        float s1 = g_sc[1] * (1.f / (float)N_NODES);
        float s2 = g_sc[2] * (1.f / (float)N_NODES);
        float mx = fmaxf(s0, fmaxf(s1, s2));
        float e0 = __expf(s0 - mx), e1 = __expf(s1 - mx), e2 = __expf(s2 - mx);
        float inv = 1.f / (e0 + e1 + e2);
        out[i] = (e0 * g_m[i] + e1 * g_m[S + i] + e2 * g_m[2 * S + i]) * inv;
    }
}

// ---------------- launch ----------------------------------------------------
extern "C" void kernel_launch(void* const* d_in, const int* in_sizes, int n_in,
                              void* d_out, int out_size) {
    const float* x      = (const float*)d_in[0];
    const float* adjs   = (const float*)d_in[1];
    const float* W_node = (const float*)d_in[2];
    const float* a_node = (const float*)d_in[3];
    const float* W_sem  = (const float*)d_in[4];
    const float* b_sem  = (const float*)d_in[5];
    const float* q_sem  = (const float*)d_in[6];
    float* out = (float*)d_out;

    // h[p,head] = x @ W_node[p,head]   (2048x512x128, 12 batches), tf32 MMA
    // (also zeroes g_sc)
    gemm_h_kernel<<<dim3(N_NODES / 64, PH), 256>>>(x, W_node);

    // s, d vectors
    sd_kernel<<<(PH * N_NODES) / 8, 256>>>(a_node);

    // fused masked attention with ONLINE softmax + ELU -> m
    attn_kernel<<<dim3(N_NODES / 64, PH), 256>>>(adjs);

    // semantic: tanh(m @ W_sem + b) . q, reduced straight into g_sc
    gemm_sem_fused<<<(NP * N_NODES) / 64, 256>>>(W_sem, b_sem, q_sem);

    // out = softmax(g_sc/N) . m   (w computed inline per thread)
    combine<<<(N_NODES * NHEADS * NHID + 255) / 256, 256>>>(out);
}

// round 16
// speedup vs baseline: 3.6270x; 1.0489x over previous
#include <cuda_runtime.h>
#include <math.h>

#define N_NODES 2048
#define NFEAT   512
#define NHID    128
#define NHEADS  4
#define NP      3
#define SHID    128
#define PH      (NP * NHEADS)     // 12
#define ALPHA_L 0.2f
#define NEGV    -9.0e15f

// attn dynamic smem layout (bytes)
#define ATT_BYTES   (64 * 68 * 4)          // 17408
#define HS_BYTES    (64 * 136 * 4)         // 34816
#define SMEM_ATTN   (ATT_BYTES + HS_BYTES + 5 * 64 * 4)   // 53504

// ---------------- scratch (static device globals; no runtime alloc) --------
__device__ float g_h [PH * N_NODES * NHID];            // h[p,head][n][d]
__device__ float g_s [PH * N_NODES];                   // h . a_src
__device__ float g_dv[PH * N_NODES];                   // h . a_dst
__device__ float g_m [NP * N_NODES * NHEADS * NHID];   // m[p][n][head*128+d]
__device__ float g_sc[NP];                             // score accumulators

// ---------------- tf32 helpers ---------------------------------------------
__device__ __forceinline__ unsigned f2tf(float f) {
    unsigned r;
    asm("cvt.rna.tf32.f32 %0, %1;" : "=r"(r) : "f"(f));
    return r;
}

__device__ __forceinline__ void mma8(float* c,
                                     unsigned a0, unsigned a1, unsigned a2, unsigned a3,
                                     unsigned b0, unsigned b1) {
    asm volatile("mma.sync.aligned.m16n8k8.row.col.f32.tf32.tf32.f32 "
                 "{%0,%1,%2,%3}, {%4,%5,%6,%7}, {%8,%9}, {%0,%1,%2,%3};"
                 : "+f"(c[0]), "+f"(c[1]), "+f"(c[2]), "+f"(c[3])
                 : "r"(a0), "r"(a1), "r"(a2), "r"(a3), "r"(b0), "r"(b1));
}

__device__ __forceinline__ float gexp(float t) {
    return t < -80.f ? 0.f : __expf(t);
}

// ---------------- tf32 GEMM core: 64x128 C tile, ldb=128, acc in regs ------
// 8 warps: 4 along M (16 rows each) x 2 along N (64 cols each).
__device__ __forceinline__ void gemm_core(const float* __restrict__ A, int lda,
                                          const float* __restrict__ B, int K,
                                          int tm, float acc[8][4]) {
    __shared__ unsigned As[64][36];    // +4 pad
    __shared__ unsigned Bs[32][136];   // +8 pad
    const int tid = threadIdx.x;
    const int warp = tid >> 5, lane = tid & 31;
    const int wi = warp & 3, wj = warp >> 2;
    const int la = lane >> 2, lb = lane & 3;

    for (int k0 = 0; k0 < K; k0 += 32) {
        __syncthreads();
#pragma unroll
        for (int it = 0; it < 2; it++) {
            int u = it * 256 + tid;
            int row = u >> 3, c4 = (u & 7) * 4;
            float4 v = *(const float4*)&A[(long)(tm + row) * lda + k0 + c4];
            As[row][c4 + 0] = f2tf(v.x); As[row][c4 + 1] = f2tf(v.y);
            As[row][c4 + 2] = f2tf(v.z); As[row][c4 + 3] = f2tf(v.w);
        }
#pragma unroll
        for (int it = 0; it < 4; it++) {
            int r = it * 8 + (tid >> 5), c4 = (tid & 31) * 4;
            float4 v = *(const float4*)&B[(long)(k0 + r) * 128 + c4];
            Bs[r][c4 + 0] = f2tf(v.x); Bs[r][c4 + 1] = f2tf(v.y);
            Bs[r][c4 + 2] = f2tf(v.z); Bs[r][c4 + 3] = f2tf(v.w);
        }
        __syncthreads();
#pragma unroll
        for (int ks = 0; ks < 4; ks++) {
            int kk = ks * 8;
            unsigned a0 = As[wi * 16 + la][kk + lb];
            unsigned a1 = As[wi * 16 + la + 8][kk + lb];
            unsigned a2 = As[wi * 16 + la][kk + lb + 4];
            unsigned a3 = As[wi * 16 + la + 8][kk + lb + 4];
#pragma unroll
            for (int nt = 0; nt < 8; nt++) {
                int cn = wj * 64 + nt * 8 + la;
                unsigned b0 = Bs[kk + lb][cn];
                unsigned b1 = Bs[kk + lb + 4][cn];
                mma8(acc[nt], a0, a1, a2, a3, b0, b1);
            }
        }
    }
}

// ---------------- h = x @ W_node (also zeroes g_sc) ------------------------
__global__ void __launch_bounds__(256) gemm_h_kernel(const float* __restrict__ x,
                                                     const float* __restrict__ Wn) {
    const int b = blockIdx.y;
    const int tm = blockIdx.x * 64;
    if (blockIdx.x == 0 && blockIdx.y == 0 && threadIdx.x < NP)
        g_sc[threadIdx.x] = 0.f;
    float acc[8][4] = {};
    gemm_core(x, NFEAT, Wn + (long)b * NFEAT * NHID, NFEAT, tm, acc);
    float* C = g_h + (long)b * N_NODES * NHID;
    const int warp = threadIdx.x >> 5, lane = threadIdx.x & 31;
    const int wi = warp & 3, wj = warp >> 2;
    const int la = lane >> 2, lb = lane & 3;
    const int row = tm + wi * 16 + la;
    const int colb = wj * 64 + lb * 2;
#pragma unroll
    for (int nt = 0; nt < 8; nt++) {
        int col = colb + nt * 8;
        *(float2*)&C[(long)row * 128 + col]       = make_float2(acc[nt][0], acc[nt][1]);
        *(float2*)&C[(long)(row + 8) * 128 + col] = make_float2(acc[nt][2], acc[nt][3]);
    }
}

// ---------------- semantic GEMM fused with score reduction ------------------
// 32x128 tile per CTA (192 CTAs -> better occupancy than 96).
// scores[p] += sum over rows,cols of tanh(m@W_sem + b)*q
__global__ void __launch_bounds__(256) gemm_sem_fused(const float* __restrict__ Ws,
                                                      const float* __restrict__ b_sem,
                                                      const float* __restrict__ q_sem) {
    const int tm = blockIdx.x * 32;
    const int p = tm >> 11;
    __shared__ unsigned As[32][36];
    __shared__ unsigned Bs[32][136];
    __shared__ float sred;
    const int tid = threadIdx.x;
    const int warp = tid >> 5, lane = tid & 31;
    const int wi = warp & 1, wj = warp >> 1;
    const int la = lane >> 2, lb = lane & 3;
    if (tid == 0) sred = 0.f;       // first sync below publishes
    float acc[4][4] = {};
    const float* A = g_m;
    const int lda = NHEADS * NHID;  // 512

    for (int k0 = 0; k0 < NHEADS * NHID; k0 += 32) {
        __syncthreads();
        {
            int row = tid >> 3, c4 = (tid & 7) * 4;
            float4 v = *(const float4*)&A[(long)(tm + row) * lda + k0 + c4];
            As[row][c4 + 0] = f2tf(v.x); As[row][c4 + 1] = f2tf(v.y);
            As[row][c4 + 2] = f2tf(v.z); As[row][c4 + 3] = f2tf(v.w);
        }
#pragma unroll
        for (int it = 0; it < 4; it++) {
            int r = it * 8 + (tid >> 5), c4 = (tid & 31) * 4;
            float4 v = *(const float4*)&Ws[(long)(k0 + r) * 128 + c4];
            Bs[r][c4 + 0] = f2tf(v.x); Bs[r][c4 + 1] = f2tf(v.y);
            Bs[r][c4 + 2] = f2tf(v.z); Bs[r][c4 + 3] = f2tf(v.w);
        }
        __syncthreads();
#pragma unroll
        for (int ks = 0; ks < 4; ks++) {
            int kk = ks * 8;
            unsigned a0 = As[wi * 16 + la][kk + lb];
            unsigned a1 = As[wi * 16 + la + 8][kk + lb];
            unsigned a2 = As[wi * 16 + la][kk + lb + 4];
            unsigned a3 = As[wi * 16 + la + 8][kk + lb + 4];
#pragma unroll
            for (int nt = 0; nt < 4; nt++) {
                int cn = wj * 32 + nt * 8 + la;
                unsigned b0 = Bs[kk + lb][cn];
                unsigned b1 = Bs[kk + lb + 4][cn];
                mma8(acc[nt], a0, a1, a2, a3, b0, b1);
            }
        }
    }
    float s = 0.f;
#pragma unroll
    for (int nt = 0; nt < 4; nt++) {
        int col = wj * 32 + lb * 2 + nt * 8;
        float b0 = b_sem[col], b1 = b_sem[col + 1];
        float q0 = q_sem[col], q1 = q_sem[col + 1];
        s += tanhf(acc[nt][0] + b0) * q0 + tanhf(acc[nt][1] + b1) * q1;
        s += tanhf(acc[nt][2] + b0) * q0 + tanhf(acc[nt][3] + b1) * q1;
    }
#pragma unroll
    for (int o = 16; o; o >>= 1) s += __shfl_xor_sync(0xffffffffu, s, o);
    if (!lane) atomicAdd(&sred, s);
    __syncthreads();
    if (tid == 0) atomicAdd(&g_sc[p], sred);
}

// ---------------- s,d = h . a_src / a_dst ----------------------------------
__global__ void __launch_bounds__(256) sd_kernel(const float* __restrict__ a_node) {
    int gwarp = (blockIdx.x * 256 + threadIdx.x) >> 5;
    int lane = threadIdx.x & 31;
    if (gwarp >= PH * N_NODES) return;
    int ph = gwarp / N_NODES;
    const float* hrow = g_h + (long)gwarp * NHID;
    const float* asrc = a_node + (long)ph * 2 * NHID;
    const float* adst = asrc + NHID;
    float4 hv = *(const float4*)&hrow[lane * 4];
    float4 as = *(const float4*)&asrc[lane * 4];
    float4 ad = *(const float4*)&adst[lane * 4];
    float ss = hv.x * as.x + hv.y * as.y + hv.z * as.z + hv.w * as.w;
    float dd = hv.x * ad.x + hv.y * ad.y + hv.z * ad.z + hv.w * ad.w;
#pragma unroll
    for (int o = 16; o; o >>= 1) {
        ss += __shfl_xor_sync(0xffffffffu, ss, o);
        dd += __shfl_xor_sync(0xffffffffu, dd, o);
    }
    if (!lane) { g_s[gwarp] = ss; g_dv[gwarp] = dd; }
}

// ---------------- fused attention, ONLINE softmax + tf32 MMA ---------------
// j-tile widened to 64: halves online-update passes / syncs / rescales.
// Dynamic smem (53504 B): att_s[64][68] | h_s[64][136] | ssm,mxs,sms,rmx,dsm[64]
__global__ void __launch_bounds__(256) attn_kernel(const float* __restrict__ adjs) {
    extern __shared__ char smem_raw[];
    unsigned (*att_s)[68]  = (unsigned(*)[68])smem_raw;
    unsigned (*h_s)[136]   = (unsigned(*)[136])(smem_raw + ATT_BYTES);
    float* ssm = (float*)(smem_raw + ATT_BYTES + HS_BYTES);
    float* mxs = ssm + 64;
    float* sms = mxs + 64;
    float* rmx = sms + 64;
    float* dsm = rmx + 64;

    const int ph = blockIdx.y;
    const int p = ph >> 2;
    const int head = ph & 3;
    const int tm = blockIdx.x * 64;
    const int tid = threadIdx.x;
    const int warp = tid >> 5, lane = tid & 31;
    const int wi = warp & 3, wj = warp >> 2;
    const int la = lane >> 2, lb = lane & 3;
    if (tid < 64) {
        ssm[tid] = g_s[(long)ph * N_NODES + tm + tid];
        mxs[tid] = NEGV;
        sms[tid] = 0.f;
        rmx[tid] = 1.f;
    }
    float acc[8][4] = {};
    const float* hbase = g_h + (long)ph * N_NODES * NHID;
    const float* abase = adjs + ((long)p * N_NODES + tm) * N_NODES;
    const int ri = tid >> 2;            // row for att build (0..63)
    const int segc = (tid & 3) * 16;    // 16-col segment within row

    for (int j0 = 0; j0 < N_NODES; j0 += 64) {
        __syncthreads();   // prev tile consumed (covers init on iter 0)
        if (tid < 64) dsm[tid] = g_dv[(long)ph * N_NODES + j0 + tid];
        // h tile 64x128 -> tf32
#pragma unroll
        for (int it = 0; it < 8; it++) {
            int r = it * 8 + (tid >> 5), c4 = (tid & 31) * 4;
            float4 hv = *(const float4*)&hbase[(long)(j0 + r) * 128 + c4];
            h_s[r][c4 + 0] = f2tf(hv.x); h_s[r][c4 + 1] = f2tf(hv.y);
            h_s[r][c4 + 2] = f2tf(hv.z); h_s[r][c4 + 3] = f2tf(hv.w);
        }
        __syncthreads();   // dsm + h visible
        // online-softmax att tile 64x64: 4 threads per row, 16 cols each
        {
            float sv = ssm[ri];
            float e[16];
            float tmax = NEGV;
#pragma unroll
            for (int g = 0; g < 4; g++) {
                float4 a = *(const float4*)&abase[(long)ri * N_NODES + j0 + segc + g * 4];
                float aa[4] = {a.x, a.y, a.z, a.w};
#pragma unroll
                for (int q = 0; q < 4; q++) {
                    float v = sv + dsm[segc + g * 4 + q];
                    v = v > 0.f ? v : ALPHA_L * v;
                    float ev = aa[q] > 0.f ? v : NEGV;
                    e[g * 4 + q] = ev;
                    tmax = fmaxf(tmax, ev);
                }
            }
            tmax = fmaxf(tmax, __shfl_xor_sync(0xffffffffu, tmax, 1));
            tmax = fmaxf(tmax, __shfl_xor_sync(0xffffffffu, tmax, 2));
            float old = mxs[ri];
            float newm = fmaxf(old, tmax);
            float r = gexp(old - newm);
            float ts = 0.f;
#pragma unroll
            for (int g = 0; g < 4; g++) {
                unsigned o[4];
#pragma unroll
                for (int q = 0; q < 4; q++) {
                    float pq = gexp(e[g * 4 + q] - newm);
                    ts += pq;
                    o[q] = f2tf(pq);
                }
                *(uint4*)&att_s[ri][segc + g * 4] = make_uint4(o[0], o[1], o[2], o[3]);
            }
            ts += __shfl_xor_sync(0xffffffffu, ts, 1);
            ts += __shfl_xor_sync(0xffffffffu, ts, 2);
            if ((tid & 3) == 0) {
                mxs[ri] = newm;
                rmx[ri] = r;
                sms[ri] = sms[ri] * r + ts;
            }
        }
        __syncthreads();   // att tile + rmx visible
        // rescale accumulators, then MMA over K=64
        {
            float r0 = rmx[wi * 16 + la];
            float r1 = rmx[wi * 16 + la + 8];
#pragma unroll
            for (int nt = 0; nt < 8; nt++) {
                acc[nt][0] *= r0; acc[nt][1] *= r0;
                acc[nt][2] *= r1; acc[nt][3] *= r1;
            }
        }
#pragma unroll
        for (int ks = 0; ks < 8; ks++) {
            int kk = ks * 8;
            unsigned a0 = att_s[wi * 16 + la][kk + lb];
            unsigned a1 = att_s[wi * 16 + la + 8][kk + lb];
            unsigned a2 = att_s[wi * 16 + la][kk + lb + 4];
            unsigned a3 = att_s[wi * 16 + la + 8][kk + lb + 4];
#pragma unroll
            for (int nt = 0; nt < 8; nt++) {
                int cn = wj * 64 + nt * 8 + la;
                unsigned b0 = h_s[kk + lb][cn];
                unsigned b1 = h_s[kk + lb + 4][cn];
                mma8(acc[nt], a0, a1, a2, a3, b0, b1);
            }
        }
    }
    // normalize + ELU epilogue, write into m[p][n][head*128 + d]
    const int row = tm + wi * 16 + la;
    const int colb = wj * 64 + lb * 2;
    const float inv0 = 1.f / sms[wi * 16 + la];
    const float inv1 = 1.f / sms[wi * 16 + la + 8];
#pragma unroll
    for (int nt = 0; nt < 8; nt++) {
        int col = head * 128 + colb + nt * 8;
        float v0 = acc[nt][0] * inv0, v1 = acc[nt][1] * inv0;
        float v2 = acc[nt][2] * inv1, v3 = acc[nt][3] * inv1;
        float e0 = v0 > 0.f ? v0 : expm1f(v0);
        float e1 = v1 > 0.f ? v1 : expm1f(v1);
        float e2 = v2 > 0.f ? v2 : expm1f(v2);
        float e3 = v3 > 0.f ? v3 : expm1f(v3);
        long b0i = ((long)p * N_NODES + row) * (NHEADS * NHID) + col;
        long b1i = ((long)p * N_NODES + row + 8) * (NHEADS * NHID) + col;
        *(float2*)&g_m[b0i] = make_float2(e0, e1);
        *(float2*)&g_m[b1i] = make_float2(e2, e3);
    }
}

// ---------------- combine (w softmax computed inline) -----------------------
__global__ void __launch_bounds__(256) combine(float* __restrict__ out) {
    int i = blockIdx.x * 256 + threadIdx.x;
    const long S = (long)N_NODES * NHEADS * NHID;
    if (i < S) {
        float s0 = g_sc[0] * (1.f / (float)N_NODES);
        float s1 = g_sc[1] * (1.f / (float)N_NODES);
        float s2 = g_sc[2] * (1.f / (float)N_NODES);
        float mx = fmaxf(s0, fmaxf(s1, s2));
        float e0 = __expf(s0 - mx), e1 = __expf(s1 - mx), e2 = __expf(s2 - mx);
        float inv = 1.f / (e0 + e1 + e2);
        out[i] = (e0 * g_m[i] + e1 * g_m[S + i] + e2 * g_m[2 * S + i]) * inv;
    }
}

// ---------------- launch ----------------------------------------------------
extern "C" void kernel_launch(void* const* d_in, const int* in_sizes, int n_in,
                              void* d_out, int out_size) {
    const float* x      = (const float*)d_in[0];
    const float* adjs   = (const float*)d_in[1];
    const float* W_node = (const float*)d_in[2];
    const float* a_node = (const float*)d_in[3];
    const float* W_sem  = (const float*)d_in[4];
    const float* b_sem  = (const float*)d_in[5];
    const float* q_sem  = (const float*)d_in[6];
    float* out = (float*)d_out;

    // allow >48KB dynamic smem for attn (host attribute set; not a stream op)
    cudaFuncSetAttribute(attn_kernel, cudaFuncAttributeMaxDynamicSharedMemorySize,
                         SMEM_ATTN);

    // h[p,head] = x @ W_node[p,head]  (tf32 MMA; also zeroes g_sc)
    gemm_h_kernel<<<dim3(N_NODES / 64, PH), 256>>>(x, W_node);

    // s, d vectors
    sd_kernel<<<(PH * N_NODES) / 8, 256>>>(a_node);

    // fused masked attention with ONLINE softmax + ELU -> m   (j-tile 64)
    attn_kernel<<<dim3(N_NODES / 64, PH), 256, SMEM_ATTN>>>(adjs);

    // semantic: tanh(m @ W_sem + b) . q -> g_sc   (32-row tiles, 192 CTAs)
    gemm_sem_fused<<<(NP * N_NODES) / 32, 256>>>(W_sem, b_sem, q_sem);

    // out = softmax(g_sc/N) . m   (w computed inline per thread)
    combine<<<(N_NODES * NHEADS * NHID + 255) / 256, 256>>>(out);
}